// round 1
// baseline (speedup 1.0000x reference)
#include <cuda_runtime.h>
#include <cstdint>

// ---------------------------------------------------------------------------
// local_graph_creator: adj = relu(tanh(3*(vec1@gEmb.T - gEmb@vec1.T))),
// then per-row top-20 (value desc, index asc) binary mask applied.
//
// Strategy:
//   prep:      vec1 = tanh_xla(3*(emb_weight[idx] @ fc1_w.T + fc1_b)); pack
//              X = [vec1 | -gEmb], Y = [gEmb | vec1]  (padded to 128-multiple)
//   gemm_adj:  adj = relu(tanh_xla(3 * X@Y.T)) written into d_out (scratch)
//   topk_mask: per row, keep top-20 entries (JAX tie semantics), zero rest.
//
// tanh_xla replicates XLA's EmitFastTanh (FMA build): clamp +-7.99881172...,
// |x|<4e-4 -> x, Eigen rational polynomial. This bitwise tie structure is
// required because tanh saturation creates thousands of exact ties per row
// and top_k breaks ties by lowest index.
// ---------------------------------------------------------------------------

#define MAX_NPAD 10112

__device__ float g_X[MAX_NPAD * 128];
__device__ float g_Y[MAX_NPAD * 128];

__device__ __forceinline__ float tanh_xla(float x) {
    const float kClamp = 7.99881172180175781f;  // XLA EmitFastTanh, with-FMA build
    float ax = fabsf(x);
    float xc = fminf(fmaxf(x, -kClamp), kClamp);
    float x2 = xc * xc;
    float p = -2.76076847742355e-16f;
    p = fmaf(x2, p, 2.00018790482477e-13f);
    p = fmaf(x2, p, -8.60467152213735e-11f);
    p = fmaf(x2, p, 5.12229709037114e-08f);
    p = fmaf(x2, p, 1.48572235717979e-05f);
    p = fmaf(x2, p, 6.37261928875436e-04f);
    p = fmaf(x2, p, 4.89352455891786e-03f);
    p = xc * p;
    float q = fmaf(x2, 1.19825839466702e-06f, 1.18534705686654e-04f);
    q = fmaf(x2, q, 2.26843463243900e-03f);
    q = fmaf(x2, q, 4.89352518554385e-03f);
    float r = p / q;
    return (ax < 0.0004f) ? x : r;
}

// ---------------------------------------------------------------------------
// prep: vec1 + pack X, Y (zero-padded rows N..npad-1)
// 256 threads = 4 rows x 64 dims per block
// ---------------------------------------------------------------------------
__global__ __launch_bounds__(256) void prep_kernel(
    const int* __restrict__ idx, const float* __restrict__ gEmb,
    const float* __restrict__ embW, const float* __restrict__ fc1w,
    const float* __restrict__ fc1b, int N, int npad) {
    __shared__ float ws[64 * 65];  // transposed + padded: ws[k*65+d] = fc1_w[d][k]
    __shared__ float bs[64];
    int t = threadIdx.x;
    for (int e = t; e < 64 * 64; e += 256) {
        int d = e >> 6, k = e & 63;
        ws[k * 65 + d] = fc1w[e];
    }
    if (t < 64) bs[t] = fc1b[t];
    __syncthreads();

    int r = t >> 6;
    int d = t & 63;
    int i = blockIdx.x * 4 + r;
    if (i >= npad) return;

    float v = 0.0f, g = 0.0f;
    if (i < N) {
        int src = idx[i];
        const float* er = embW + (size_t)src * 64;
        float acc = 0.0f;
#pragma unroll
        for (int k = 0; k < 64; k++) acc = fmaf(er[k], ws[k * 65 + d], acc);
        acc += bs[d];
        v = tanh_xla(3.0f * acc);
        g = gEmb[(size_t)i * 64 + d];
    }
    g_X[(size_t)i * 128 + d]      = v;
    g_X[(size_t)i * 128 + 64 + d] = -g;
    g_Y[(size_t)i * 128 + d]      = g;
    g_Y[(size_t)i * 128 + 64 + d] = v;
}

// ---------------------------------------------------------------------------
// gemm_adj: adj = relu(tanh_xla(3 * X @ Y^T)) -> out (N x N)
// 128x128 tile, K=128 in 4 chunks of 32, 256 threads, 8x8 microtile.
// ---------------------------------------------------------------------------
__global__ __launch_bounds__(256) void gemm_adj_kernel(float* __restrict__ out,
                                                       int N) {
    __shared__ float As[32 * 132];
    __shared__ float Bs[32 * 132];
    const int t = threadIdx.x;
    const int tx = t & 15, ty = t >> 4;
    const int bm = blockIdx.y * 128, bn = blockIdx.x * 128;

    float acc[8][8];
#pragma unroll
    for (int i = 0; i < 8; i++)
#pragma unroll
        for (int j = 0; j < 8; j++) acc[i][j] = 0.0f;

    const float4* Xv = reinterpret_cast<const float4*>(g_X);
    const float4* Yv = reinterpret_cast<const float4*>(g_Y);

#pragma unroll
    for (int kc = 0; kc < 128; kc += 32) {
#pragma unroll
        for (int i = 0; i < 4; i++) {
            int q = t + i * 256;     // 0..1023
            int r = q >> 3;          // row within tile 0..127
            int k4 = q & 7;          // float4 index within 32-wide k chunk
            float4 a = Xv[(size_t)(bm + r) * 32 + (kc >> 2) + k4];
            As[(k4 * 4 + 0) * 132 + r] = a.x;
            As[(k4 * 4 + 1) * 132 + r] = a.y;
            As[(k4 * 4 + 2) * 132 + r] = a.z;
            As[(k4 * 4 + 3) * 132 + r] = a.w;
            float4 b = Yv[(size_t)(bn + r) * 32 + (kc >> 2) + k4];
            Bs[(k4 * 4 + 0) * 132 + r] = b.x;
            Bs[(k4 * 4 + 1) * 132 + r] = b.y;
            Bs[(k4 * 4 + 2) * 132 + r] = b.z;
            Bs[(k4 * 4 + 3) * 132 + r] = b.w;
        }
        __syncthreads();
#pragma unroll
        for (int k = 0; k < 32; k++) {
            float4 a0 = *(const float4*)&As[k * 132 + ty * 8];
            float4 a1 = *(const float4*)&As[k * 132 + ty * 8 + 4];
            float4 b0 = *(const float4*)&Bs[k * 132 + tx * 8];
            float4 b1 = *(const float4*)&Bs[k * 132 + tx * 8 + 4];
            float ra[8] = {a0.x, a0.y, a0.z, a0.w, a1.x, a1.y, a1.z, a1.w};
            float rb[8] = {b0.x, b0.y, b0.z, b0.w, b1.x, b1.y, b1.z, b1.w};
#pragma unroll
            for (int i = 0; i < 8; i++)
#pragma unroll
                for (int j = 0; j < 8; j++)
                    acc[i][j] = fmaf(ra[i], rb[j], acc[i][j]);
        }
        __syncthreads();
    }

    const int i0 = bm + ty * 8;
    const int j0 = bn + tx * 8;
    if (bm + 128 <= N && bn + 128 <= N) {
#pragma unroll
        for (int ii = 0; ii < 8; ii++) {
            float4 v0, v1;
            v0.x = fmaxf(tanh_xla(3.0f * acc[ii][0]), 0.0f);
            v0.y = fmaxf(tanh_xla(3.0f * acc[ii][1]), 0.0f);
            v0.z = fmaxf(tanh_xla(3.0f * acc[ii][2]), 0.0f);
            v0.w = fmaxf(tanh_xla(3.0f * acc[ii][3]), 0.0f);
            v1.x = fmaxf(tanh_xla(3.0f * acc[ii][4]), 0.0f);
            v1.y = fmaxf(tanh_xla(3.0f * acc[ii][5]), 0.0f);
            v1.z = fmaxf(tanh_xla(3.0f * acc[ii][6]), 0.0f);
            v1.w = fmaxf(tanh_xla(3.0f * acc[ii][7]), 0.0f);
            float* p = out + (size_t)(i0 + ii) * N + j0;
            *(float4*)p = v0;
            *(float4*)(p + 4) = v1;
        }
    } else {
#pragma unroll
        for (int ii = 0; ii < 8; ii++) {
            if (i0 + ii >= N) continue;
#pragma unroll
            for (int jj = 0; jj < 8; jj++) {
                if (j0 + jj >= N) continue;
                out[(size_t)(i0 + ii) * N + (j0 + jj)] =
                    fmaxf(tanh_xla(3.0f * acc[ii][jj]), 0.0f);
            }
        }
    }
}

// ---------------------------------------------------------------------------
// topk_mask: one CTA per row, in place on out.
// Fast path: >=20 ties at the row max -> 20 smallest tied indices (ballot scan).
// General path: per-thread top-20 candidates + 20 block argmax iterations,
// key = (value_bits << 32) | ~index  (value desc, index asc).
// ---------------------------------------------------------------------------
__global__ __launch_bounds__(256) void topk_mask_kernel(float* __restrict__ out,
                                                        int N) {
    const int row = blockIdx.x;
    const int t = threadIdx.x;
    __shared__ __align__(16) float srow[10016];
    __shared__ unsigned long long red[256];
    __shared__ float swmax[8];
    __shared__ int sWarpCnt[8];
    __shared__ float sM1;
    __shared__ int scnt;
    __shared__ int selIdx[20];
    __shared__ float selVal[20];

    float* rowp = out + (size_t)row * N;
    const int nv = N >> 2;  // N assumed multiple of 4 (10000)

    float lmax = 0.0f;  // adj >= 0
    for (int q = t; q < nv; q += 256) {
        float4 v = reinterpret_cast<float4*>(rowp)[q];
        reinterpret_cast<float4*>(srow)[q] = v;
        lmax = fmaxf(lmax, fmaxf(fmaxf(v.x, v.y), fmaxf(v.z, v.w)));
    }
#pragma unroll
    for (int s = 16; s; s >>= 1)
        lmax = fmaxf(lmax, __shfl_xor_sync(0xffffffffu, lmax, s));
    if ((t & 31) == 0) swmax[t >> 5] = lmax;
    if (t == 0) scnt = 0;
    __syncthreads();
    if (t == 0) {
        float m = swmax[0];
#pragma unroll
        for (int w = 1; w < 8; w++) m = fmaxf(m, swmax[w]);
        sM1 = m;
    }
    __syncthreads();
    const float M1 = sM1;

    int lc = 0;
    for (int q = t; q < N; q += 256) lc += (srow[q] == M1) ? 1 : 0;
#pragma unroll
    for (int s = 16; s; s >>= 1) lc += __shfl_xor_sync(0xffffffffu, lc, s);
    if ((t & 31) == 0) atomicAdd(&scnt, lc);
    __syncthreads();
    const int cnt = scnt;

    if (cnt >= 20) {
        // ---- fast path: top-20 = 20 smallest indices with value == M1 ----
        int found = 0;
        for (int base = 0; base < N && found < 20; base += 256) {
            int j = base + t;
            bool f = (j < N) && (srow[j] == M1);
            unsigned b = __ballot_sync(0xffffffffu, f);
            if ((t & 31) == 0) sWarpCnt[t >> 5] = __popc(b);
            __syncthreads();
            int wid = t >> 5;
            int offs = found;
#pragma unroll
            for (int w = 0; w < 8; w++)
                if (w < wid) offs += sWarpCnt[w];
            int myrank = offs + __popc(b & ((1u << (t & 31)) - 1u));
            if (f && myrank < 20) {
                selIdx[myrank] = j;
                selVal[myrank] = M1;
            }
            int tot = 0;
#pragma unroll
            for (int w = 0; w < 8; w++) tot += sWarpCnt[w];
            found += tot;
            __syncthreads();
        }
    } else {
        // ---- general path ----
        unsigned long long cand[20];
#pragma unroll
        for (int c = 0; c < 20; c++) cand[c] = 0ull;
        unsigned long long curMin = 0ull;
        for (int q = t; q < N; q += 256) {
            unsigned vb = __float_as_uint(srow[q]);  // srow >= 0 -> monotonic
            unsigned long long key =
                ((unsigned long long)vb << 32) |
                (unsigned long long)(0xFFFFFFFFu - (unsigned)q);
            if (key > curMin) {
                bool done = false;
#pragma unroll
                for (int c = 0; c < 20; c++) {
                    if (!done && cand[c] == curMin) {
                        cand[c] = key;
                        done = true;
                    }
                }
                unsigned long long m = cand[0];
#pragma unroll
                for (int c = 1; c < 20; c++) m = (cand[c] < m) ? cand[c] : m;
                curMin = m;
            }
        }
        for (int it = 0; it < 20; it++) {
            unsigned long long m = cand[0];
#pragma unroll
            for (int c = 1; c < 20; c++) m = (cand[c] > m) ? cand[c] : m;
            red[t] = m;
            __syncthreads();
            for (int s = 128; s >= 32; s >>= 1) {
                if (t < s) {
                    unsigned long long o = red[t + s];
                    if (o > red[t]) red[t] = o;
                }
                __syncthreads();
            }
            if (t < 32) {
                unsigned long long g = red[t];
#pragma unroll
                for (int s = 16; s; s >>= 1) {
                    unsigned long long o = __shfl_xor_sync(0xffffffffu, g, s);
                    if (o > g) g = o;
                }
                if (t == 0) red[0] = g;
            }
            __syncthreads();
            unsigned long long g = red[0];
            if (t == 0) {
                if (g != 0ull) {
                    selIdx[it] =
                        (int)(0xFFFFFFFFu - (unsigned)(g & 0xFFFFFFFFull));
                    selVal[it] = __uint_as_float((unsigned)(g >> 32));
                } else {
                    selIdx[it] = 0;
                    selVal[it] = 0.0f;
                }
            }
            if (g != 0ull) {
#pragma unroll
                for (int c = 0; c < 20; c++)
                    if (cand[c] == g) cand[c] = 0ull;
            }
            __syncthreads();
        }
    }

    // write back: zero the row, then scatter the 20 kept entries
    float4 z = make_float4(0.0f, 0.0f, 0.0f, 0.0f);
    for (int q = t; q < nv; q += 256) reinterpret_cast<float4*>(rowp)[q] = z;
    __syncthreads();
    if (t < 20) rowp[selIdx[t]] = selVal[t];
}

// ---------------------------------------------------------------------------
extern "C" void kernel_launch(void* const* d_in, const int* in_sizes, int n_in,
                              void* d_out, int out_size) {
    const int* idx = (const int*)d_in[0];
    const float* gEmb = (const float*)d_in[1];
    const float* embW = (const float*)d_in[2];
    const float* fc1w = (const float*)d_in[3];
    const float* fc1b = (const float*)d_in[4];
    float* out = (float*)d_out;

    int N = in_sizes[0];
    int tiles = (N + 127) / 128;
    int npad = tiles * 128;

    prep_kernel<<<npad / 4, 256>>>(idx, gEmb, embW, fc1w, fc1b, N, npad);
    gemm_adj_kernel<<<dim3(tiles, tiles), 256>>>(out, N);
    topk_mask_kernel<<<N, 256>>>(out, N);
}

// round 2
// speedup vs baseline: 3.0831x; 3.0831x over previous
#include <cuda_runtime.h>
#include <cstdint>

// ---------------------------------------------------------------------------
// local_graph_creator: adj = relu(tanh(3*(vec1@gEmb.T - gEmb@vec1.T))),
// then per-row top-20 (value desc, index asc) binary mask applied.
//
//   prep:      vec1 = tanh_xla(3*fc1(emb)); pack TRANSPOSED
//              Xt[k][i] = [vec1 | -gEmb], Yt[k][i] = [gEmb | vec1]; zero rowmax
//   gemm_adj:  triangular (bm<=bn): t = tanh_xla(3 * X@Y.T);
//              upper tile <- max(t,0), lower tile <- max(-t,0) (a antisym
//              bitwise, tanh_xla exactly odd). Row-max fused via atomics.
//   topk_mask: M1 = rowmax; ordered ballot scan for 20 smallest tied indices
//              (saturation ties); general fallback; zero + scatter.
//
// tanh_xla replicates XLA EmitFastTanh (FMA build) bitwise.
// ---------------------------------------------------------------------------

#define MAX_NPAD 10112

__device__ float g_Xt[128 * MAX_NPAD];   // [k][i]
__device__ float g_Yt[128 * MAX_NPAD];   // [k][i]
__device__ unsigned g_rowmax[MAX_NPAD];  // float bits, values >= 0

__device__ __forceinline__ float tanh_xla(float x) {
    const float kClamp = 7.99881172180175781f;
    float ax = fabsf(x);
    float xc = fminf(fmaxf(x, -kClamp), kClamp);
    float x2 = xc * xc;
    float p = -2.76076847742355e-16f;
    p = fmaf(x2, p, 2.00018790482477e-13f);
    p = fmaf(x2, p, -8.60467152213735e-11f);
    p = fmaf(x2, p, 5.12229709037114e-08f);
    p = fmaf(x2, p, 1.48572235717979e-05f);
    p = fmaf(x2, p, 6.37261928875436e-04f);
    p = fmaf(x2, p, 4.89352455891786e-03f);
    p = xc * p;
    float q = fmaf(x2, 1.19825839466702e-06f, 1.18534705686654e-04f);
    q = fmaf(x2, q, 2.26843463243900e-03f);
    q = fmaf(x2, q, 4.89352518554385e-03f);
    float r = p / q;
    return (ax < 0.0004f) ? x : r;
}

__device__ __forceinline__ unsigned sanitize_pos(float v) {
    // values are >=0 by construction except possible -0.0; map -0 -> +0 bits
    unsigned u = __float_as_uint(v);
    return (u == 0x80000000u) ? 0u : u;
}

// ---------------------------------------------------------------------------
// prep: vec1 + pack transposed Xt, Yt (zero-padded cols N..npad-1); zero rowmax
// ---------------------------------------------------------------------------
__global__ __launch_bounds__(256) void prep_kernel(
    const int* __restrict__ idx, const float* __restrict__ gEmb,
    const float* __restrict__ embW, const float* __restrict__ fc1w,
    const float* __restrict__ fc1b, int N, int npad) {
    __shared__ float ws[64 * 65];
    __shared__ float bs[64];
    int t = threadIdx.x;
    int gid = blockIdx.x * 256 + t;
    if (gid < npad) g_rowmax[gid] = 0u;

    for (int e = t; e < 64 * 64; e += 256) {
        int d = e >> 6, k = e & 63;
        ws[k * 65 + d] = fc1w[e];
    }
    if (t < 64) bs[t] = fc1b[t];
    __syncthreads();

    int r = t >> 6;
    int d = t & 63;
    int i = blockIdx.x * 4 + r;
    if (i >= npad) return;

    float v = 0.0f, g = 0.0f;
    if (i < N) {
        int src = idx[i];
        const float* er = embW + (size_t)src * 64;
        float acc = 0.0f;
#pragma unroll
        for (int k = 0; k < 64; k++) acc = fmaf(er[k], ws[k * 65 + d], acc);
        acc += bs[d];
        v = tanh_xla(3.0f * acc);
        g = gEmb[(size_t)i * 64 + d];
    }
    g_Xt[(size_t)d * npad + i]        = v;
    g_Xt[(size_t)(64 + d) * npad + i] = -g;
    g_Yt[(size_t)d * npad + i]        = g;
    g_Yt[(size_t)(64 + d) * npad + i] = v;
}

// ---------------------------------------------------------------------------
// gemm_adj: triangular tiles, whole K=128 resident in smem.
// smem: As[128][128], Bs[128][128] (fp32). 256 threads, 8x8 microtile in
// 4+4 split quadrants. Epilogue: tanh, dual writes, fused row-max.
// ---------------------------------------------------------------------------
__global__ __launch_bounds__(256, 1) void gemm_adj_kernel(float* __restrict__ out,
                                                          int N, int npad) {
    const int bxi = blockIdx.x, byi = blockIdx.y;
    if (byi > bxi) return;
    const int bm = byi * 128, bn = bxi * 128;
    const bool diag = (bxi == byi);

    extern __shared__ float sm[];
    float* Asf = sm;             // [k][r] 128*128
    float* Bsf = sm + 16384;     // [k][r]

    const int t = threadIdx.x;
    const int tx = t & 15, ty = t >> 4;
    const int lane = t & 31;
    const int warp = t >> 5;

    // ---- load whole K slab (coalesced float4) ----
    {
        const float4* Xv = reinterpret_cast<const float4*>(g_Xt);
        const float4* Yv = reinterpret_cast<const float4*>(g_Yt);
        float4* As4 = reinterpret_cast<float4*>(Asf);
        float4* Bs4 = reinterpret_cast<float4*>(Bsf);
        const int np4 = npad >> 2;
        const int bm4 = bm >> 2, bn4 = bn >> 2;
#pragma unroll
        for (int e = 0; e < 16; e++) {
            int q = e * 256 + t;      // 0..4095
            int k = q >> 5;           // 0..127
            int r4 = q & 31;
            As4[q] = Xv[(size_t)k * np4 + bm4 + r4];
            Bs4[q] = Yv[(size_t)k * np4 + bn4 + r4];
        }
    }
    __syncthreads();

    float acc[8][8];
#pragma unroll
    for (int i = 0; i < 8; i++)
#pragma unroll
        for (int j = 0; j < 8; j++) acc[i][j] = 0.0f;

    // ---- main K loop (FFMA bound, conflict-free LDS) ----
#pragma unroll 4
    for (int k = 0; k < 128; k++) {
        const float* ak = Asf + k * 128;
        const float* bk = Bsf + k * 128;
        float4 a0 = *(const float4*)(ak + ty * 4);
        float4 a1 = *(const float4*)(ak + 64 + ty * 4);
        float4 b0 = *(const float4*)(bk + tx * 4);
        float4 b1 = *(const float4*)(bk + 64 + tx * 4);
        float ra[8] = {a0.x, a0.y, a0.z, a0.w, a1.x, a1.y, a1.z, a1.w};
        float rb[8] = {b0.x, b0.y, b0.z, b0.w, b1.x, b1.y, b1.z, b1.w};
#pragma unroll
        for (int i = 0; i < 8; i++)
#pragma unroll
            for (int j = 0; j < 8; j++)
                acc[i][j] = fmaf(ra[i], rb[j], acc[i][j]);
    }

    // ---- epilogue: t = tanh_xla(3*acc) in place ----
#pragma unroll
    for (int i = 0; i < 8; i++)
#pragma unroll
        for (int j = 0; j < 8; j++) acc[i][j] = tanh_xla(3.0f * acc[i][j]);

    __syncthreads();  // done reading As/Bs; overlays follow

    // smem overlays
    float* sT = sm;                 // [128][33] staging for transposed tile
    float* sMaxI = sm + 16384;      // [128]
    float* sPartJ = sm + 16384 + 128;  // [8][132]

    // row indices / col indices of this thread
    int R[8], C[8];
#pragma unroll
    for (int u = 0; u < 4; u++) {
        R[u] = ty * 4 + u;       R[4 + u] = 64 + ty * 4 + u;
        C[u] = tx * 4 + u;       C[4 + u] = 64 + tx * 4 + u;
    }

    // ---- I-row maxes (upper values max(t,0)) via shfl over tx group ----
#pragma unroll
    for (int ii = 0; ii < 8; ii++) {
        float m = acc[ii][0];
#pragma unroll
        for (int jj = 1; jj < 8; jj++) m = fmaxf(m, acc[ii][jj]);
        m = fmaxf(m, 0.0f);
#pragma unroll
        for (int s = 1; s < 16; s <<= 1)
            m = fmaxf(m, __shfl_xor_sync(0xffffffffu, m, s));
        if (tx == 0) sMaxI[R[ii]] = m;
    }

    // ---- J-col maxes of lower values max(-t,0) ----
    if (!diag) {
        float mj[8];
#pragma unroll
        for (int jj = 0; jj < 8; jj++) {
            float m = -acc[0][jj];
#pragma unroll
            for (int ii = 1; ii < 8; ii++) m = fmaxf(m, -acc[ii][jj]);
            m = fmaxf(m, 0.0f);
            m = fmaxf(m, __shfl_xor_sync(0xffffffffu, m, 16));
            mj[jj] = m;
        }
        if (lane < 16) {
#pragma unroll
            for (int jj = 0; jj < 8; jj++) sPartJ[warp * 132 + C[jj]] = mj[jj];
        }
    }

    // ---- direct (upper) tile write ----
    const bool fastM = (bm + 128 <= N), fastN = (bn + 128 <= N);
    if (fastM && fastN) {
#pragma unroll
        for (int ii = 0; ii < 8; ii++) {
            float4 v0, v1;
            v0.x = fmaxf(acc[ii][0], 0.0f); v0.y = fmaxf(acc[ii][1], 0.0f);
            v0.z = fmaxf(acc[ii][2], 0.0f); v0.w = fmaxf(acc[ii][3], 0.0f);
            v1.x = fmaxf(acc[ii][4], 0.0f); v1.y = fmaxf(acc[ii][5], 0.0f);
            v1.z = fmaxf(acc[ii][6], 0.0f); v1.w = fmaxf(acc[ii][7], 0.0f);
            float* p = out + (size_t)(bm + R[ii]) * N + bn;
            *(float4*)(p + tx * 4) = v0;
            *(float4*)(p + 64 + tx * 4) = v1;
        }
    } else {
#pragma unroll
        for (int ii = 0; ii < 8; ii++) {
            int gi = bm + R[ii];
            if (gi >= N) continue;
#pragma unroll
            for (int jj = 0; jj < 8; jj++) {
                int gj = bn + C[jj];
                if (gj >= N) continue;
                out[(size_t)gi * N + gj] = fmaxf(acc[ii][jj], 0.0f);
            }
        }
    }

    __syncthreads();

    // ---- global row-max atomics ----
    if (t < 128) {
        int gi = bm + t;
        if (gi < npad) atomicMax(&g_rowmax[gi], sanitize_pos(sMaxI[t]));
        if (!diag) {
            float m = sPartJ[t];
#pragma unroll
            for (int w = 1; w < 8; w++) m = fmaxf(m, sPartJ[w * 132 + t]);
            int gj = bn + t;
            if (gj < npad) atomicMax(&g_rowmax[gj], sanitize_pos(m));
        }
    }

    // ---- transposed (lower) tile write via smem staging, 4 chunks of 32 ----
    if (!diag) {
        __syncthreads();  // sT overlays As; also sPartJ reads done
#pragma unroll
        for (int c = 0; c < 4; c++) {
            int g = c >> 1, h = c & 1;
            if ((tx >> 3) == h) {
                int jl0 = tx * 4 + 64 * g - 32 * c;  // in [0,28]
#pragma unroll
                for (int ii = 0; ii < 8; ii++)
#pragma unroll
                    for (int v = 0; v < 4; v++)
                        sT[R[ii] * 33 + jl0 + v] =
                            fmaxf(-acc[ii][g * 4 + v], 0.0f);
            }
            __syncthreads();
            if (fastM && fastN) {
#pragma unroll
                for (int e = 0; e < 16; e++) {
                    int lin = e * 256 + t;
                    int jl = lin >> 7;
                    int i = lin & 127;
                    out[(size_t)(bn + c * 32 + jl) * N + bm + i] =
                        sT[i * 33 + jl];
                }
            } else {
#pragma unroll
                for (int e = 0; e < 16; e++) {
                    int lin = e * 256 + t;
                    int jl = lin >> 7;
                    int i = lin & 127;
                    int gj = bn + c * 32 + jl;
                    int gi = bm + i;
                    if (gj < N && gi < N)
                        out[(size_t)gj * N + gi] = sT[i * 33 + jl];
                }
            }
            __syncthreads();
        }
    }
}

// ---------------------------------------------------------------------------
// topk_mask: one CTA per row. M1 from fused rowmax. Fast path: ordered ballot
// scan for 20 smallest indices with v==M1. Rare general path otherwise.
// ---------------------------------------------------------------------------
__global__ __launch_bounds__(256) void topk_mask_kernel(float* __restrict__ out,
                                                        int N) {
    const int row = blockIdx.x;
    const int t = threadIdx.x;
    __shared__ int sWarpCnt[8];
    __shared__ unsigned long long red[256];
    __shared__ int selIdx[20];
    __shared__ float selVal[20];

    float* rowp = out + (size_t)row * N;
    const float M1 = __uint_as_float(g_rowmax[row]);
    const int nv = N >> 2;

    int found = 0;
    for (int base = 0; base < N; base += 256) {
        int j = base + t;
        bool f = (j < N) && (rowp[j] == M1);
        unsigned b = __ballot_sync(0xffffffffu, f);
        if ((t & 31) == 0) sWarpCnt[t >> 5] = __popc(b);
        __syncthreads();
        int wid = t >> 5;
        int offs = found;
#pragma unroll
        for (int w = 0; w < 8; w++)
            if (w < wid) offs += sWarpCnt[w];
        int myrank = offs + __popc(b & ((1u << (t & 31)) - 1u));
        if (f && myrank < 20) {
            selIdx[myrank] = j;
            selVal[myrank] = M1;
        }
        int tot = 0;
#pragma unroll
        for (int w = 0; w < 8; w++) tot += sWarpCnt[w];
        found += tot;
        __syncthreads();
        if (found >= 20) break;
    }

    if (found < 20) {
        // ---- general path (rare): full row, key = value desc, index asc ----
        unsigned long long cand[20];
#pragma unroll
        for (int c = 0; c < 20; c++) cand[c] = 0ull;
        unsigned long long curMin = 0ull;
        for (int q = t; q < N; q += 256) {
            unsigned vb = __float_as_uint(rowp[q]);
            if (vb == 0x80000000u) vb = 0u;  // -0 -> +0
            unsigned long long key =
                ((unsigned long long)vb << 32) |
                (unsigned long long)(0xFFFFFFFFu - (unsigned)q);
            if (key > curMin) {
                bool done = false;
#pragma unroll
                for (int c = 0; c < 20; c++) {
                    if (!done && cand[c] == curMin) {
                        cand[c] = key;
                        done = true;
                    }
                }
                unsigned long long m = cand[0];
#pragma unroll
                for (int c = 1; c < 20; c++) m = (cand[c] < m) ? cand[c] : m;
                curMin = m;
            }
        }
        for (int it = 0; it < 20; it++) {
            unsigned long long m = cand[0];
#pragma unroll
            for (int c = 1; c < 20; c++) m = (cand[c] > m) ? cand[c] : m;
            red[t] = m;
            __syncthreads();
            for (int s = 128; s >= 32; s >>= 1) {
                if (t < s) {
                    unsigned long long o = red[t + s];
                    if (o > red[t]) red[t] = o;
                }
                __syncthreads();
            }
            if (t < 32) {
                unsigned long long g = red[t];
#pragma unroll
                for (int s = 16; s; s >>= 1) {
                    unsigned long long o = __shfl_xor_sync(0xffffffffu, g, s);
                    if (o > g) g = o;
                }
                if (t == 0) red[0] = g;
            }
            __syncthreads();
            unsigned long long g = red[0];
            if (t == 0) {
                if (g != 0ull) {
                    selIdx[it] =
                        (int)(0xFFFFFFFFu - (unsigned)(g & 0xFFFFFFFFull));
                    selVal[it] = __uint_as_float((unsigned)(g >> 32));
                } else {
                    selIdx[it] = 0;
                    selVal[it] = 0.0f;
                }
            }
            if (g != 0ull) {
#pragma unroll
                for (int c = 0; c < 20; c++)
                    if (cand[c] == g) cand[c] = 0ull;
            }
            __syncthreads();
        }
    }
    __syncthreads();

    // zero the row, then scatter the kept entries
    float4 z = make_float4(0.0f, 0.0f, 0.0f, 0.0f);
    for (int q = t; q < nv; q += 256) reinterpret_cast<float4*>(rowp)[q] = z;
    __syncthreads();
    if (t < 20) rowp[selIdx[t]] = selVal[t];
}

// ---------------------------------------------------------------------------
extern "C" void kernel_launch(void* const* d_in, const int* in_sizes, int n_in,
                              void* d_out, int out_size) {
    const int* idx = (const int*)d_in[0];
    const float* gEmb = (const float*)d_in[1];
    const float* embW = (const float*)d_in[2];
    const float* fc1w = (const float*)d_in[3];
    const float* fc1b = (const float*)d_in[4];
    float* out = (float*)d_out;

    int N = in_sizes[0];
    int tiles = (N + 127) / 128;
    int npad = tiles * 128;

    static bool attr_set = false;
    if (!attr_set) {
        cudaFuncSetAttribute(gemm_adj_kernel,
                             cudaFuncAttributeMaxDynamicSharedMemorySize,
                             131072);
        attr_set = true;
    }

    prep_kernel<<<npad / 4, 256>>>(idx, gEmb, embW, fc1w, fc1b, N, npad);
    gemm_adj_kernel<<<dim3(tiles, tiles), 256, 131072>>>(out, N, npad);
    topk_mask_kernel<<<N, 256>>>(out, N);
}

// round 3
// speedup vs baseline: 3.6124x; 1.1717x over previous
#include <cuda_runtime.h>
#include <cstdint>

// ---------------------------------------------------------------------------
// local_graph_creator: adj = relu(tanh(3*(vec1@gEmb.T - gEmb@vec1.T))),
// then per-row top-20 (value desc, index asc) binary mask applied.
//
//   prep:      vec1 = tanh_xla(3*fc1(emb)); pack TRANSPOSED (coalesced via
//              smem transpose) Xt[k][i]=[vec1|-gEmb], Yt[k][i]=[gEmb|vec1];
//              zero rowmax + fallback counter.
//   gemm_adj:  triangular 1-D grid; t = tanh_xla(3 * X@Y.T) (bitwise identical
//              FMA chain to prior rounds). NO adj materialization: writes
//              (a) zeros into d_out (hidden under compute), (b) saturation
//              bitmask g_mask[i][j] = (bits(t)==bits(satval)) for both the
//              tile and its antisymmetric transpose, (c) fused row-max.
//   topk_mask: warp per row. If rowmax==satval: scan mask, scatter satval at
//              the 20 smallest set-bit indices (JAX tie semantics). Else /
//              if <20 ties: flag row for exact fallback.
//   fallback:  recompute the full row (same FMA chain), exact top-20 with
//              (value desc, index asc) keys, scatter. Expected 0 rows.
// ---------------------------------------------------------------------------

#define MAX_NPAD 10112

__device__ float g_Xt[128 * MAX_NPAD];                 // [k][i]
__device__ float g_Yt[128 * MAX_NPAD];                 // [k][i]
__device__ unsigned g_rowmax[MAX_NPAD];                // float bits, >= 0
__device__ unsigned g_mask[MAX_NPAD * (MAX_NPAD / 32)];// tie bitmask
__device__ int g_fb_cnt;
__device__ int g_fb_list[MAX_NPAD];

__device__ __forceinline__ float tanh_xla(float x) {
    const float kClamp = 7.99881172180175781f;
    float ax = fabsf(x);
    float xc = fminf(fmaxf(x, -kClamp), kClamp);
    float x2 = xc * xc;
    float p = -2.76076847742355e-16f;
    p = fmaf(x2, p, 2.00018790482477e-13f);
    p = fmaf(x2, p, -8.60467152213735e-11f);
    p = fmaf(x2, p, 5.12229709037114e-08f);
    p = fmaf(x2, p, 1.48572235717979e-05f);
    p = fmaf(x2, p, 6.37261928875436e-04f);
    p = fmaf(x2, p, 4.89352455891786e-03f);
    p = xc * p;
    float q = fmaf(x2, 1.19825839466702e-06f, 1.18534705686654e-04f);
    q = fmaf(x2, q, 2.26843463243900e-03f);
    q = fmaf(x2, q, 4.89352518554385e-03f);
    float r = p / q;
    return (ax < 0.0004f) ? x : r;
}

__device__ __forceinline__ float sat_val() { return tanh_xla(8.0f); }

__device__ __forceinline__ unsigned sanitize_pos(float v) {
    unsigned u = __float_as_uint(v);
    return (u == 0x80000000u) ? 0u : u;
}

__device__ __forceinline__ void cp_async16(uint32_t saddr, const void* gaddr) {
    asm volatile("cp.async.cg.shared.global [%0], [%1], 16;" ::
                 "r"(saddr), "l"(gaddr));
}

// ---------------------------------------------------------------------------
// prep: 64 rows per block. Phase A: compute vec1 into smem (transposed).
// Phase B: load gEmb into smem (overlaying ws). Phase C: coalesced writes of
// Xt/Yt. Also zeroes rowmax + fallback counter.
// ---------------------------------------------------------------------------
__global__ __launch_bounds__(256) void prep_kernel(
    const int* __restrict__ idx, const float* __restrict__ gEmb,
    const float* __restrict__ embW, const float* __restrict__ fc1w,
    const float* __restrict__ fc1b, int N, int npad) {
    __shared__ float ws[64 * 65];   // phase A: fc1w^T; phase B/C: sg
    __shared__ float sv[64 * 65];   // vec1 transposed [d][i_local]
    __shared__ float bs[64];
    const int t = threadIdx.x;
    const int bi0 = blockIdx.x * 64;

    int gid = blockIdx.x * 256 + t;
    if (gid < npad) g_rowmax[gid] = 0u;
    if (blockIdx.x == 0 && t == 0) g_fb_cnt = 0;

    for (int e = t; e < 64 * 64; e += 256) {
        int d = e >> 6, k = e & 63;
        ws[k * 65 + d] = fc1w[e];
    }
    if (t < 64) bs[t] = fc1b[t];
    __syncthreads();

    const int d = t & 63;
    const int rq = t >> 6;  // 0..3
#pragma unroll
    for (int rr = 0; rr < 16; rr++) {
        int il = rr * 4 + rq;
        int i = bi0 + il;
        float v = 0.0f;
        if (i < N) {
            int src = idx[i];
            const float* er = embW + (size_t)src * 64;
            float acc = 0.0f;
#pragma unroll
            for (int k = 0; k < 64; k++) acc = fmaf(er[k], ws[k * 65 + d], acc);
            acc += bs[d];
            v = tanh_xla(3.0f * acc);
        }
        sv[d * 65 + il] = v;
    }
    __syncthreads();

    // Phase B: gEmb into ws (as sg)
#pragma unroll
    for (int rr = 0; rr < 16; rr++) {
        int il = rr * 4 + rq;
        int i = bi0 + il;
        float g = (i < N) ? gEmb[(size_t)i * 64 + d] : 0.0f;
        ws[d * 65 + il] = g;
    }
    __syncthreads();

    // Phase C: coalesced float4 writes of Xt/Yt rows
#pragma unroll
    for (int p = 0; p < 8; p++) {
        int e = p * 256 + t;     // 0..2047
        int dd = e >> 4;         // 0..127
        int i4 = (e & 15) * 4;   // 0..60
        float4 xv, yv;
        if (dd < 64) {
            xv.x = sv[dd * 65 + i4 + 0]; xv.y = sv[dd * 65 + i4 + 1];
            xv.z = sv[dd * 65 + i4 + 2]; xv.w = sv[dd * 65 + i4 + 3];
            yv.x = ws[dd * 65 + i4 + 0]; yv.y = ws[dd * 65 + i4 + 1];
            yv.z = ws[dd * 65 + i4 + 2]; yv.w = ws[dd * 65 + i4 + 3];
        } else {
            int dl = dd - 64;
            xv.x = -ws[dl * 65 + i4 + 0]; xv.y = -ws[dl * 65 + i4 + 1];
            xv.z = -ws[dl * 65 + i4 + 2]; xv.w = -ws[dl * 65 + i4 + 3];
            yv.x = sv[dl * 65 + i4 + 0];  yv.y = sv[dl * 65 + i4 + 1];
            yv.z = sv[dl * 65 + i4 + 2];  yv.w = sv[dl * 65 + i4 + 3];
        }
        *(float4*)&g_Xt[(size_t)dd * npad + bi0 + i4] = xv;
        *(float4*)&g_Yt[(size_t)dd * npad + bi0 + i4] = yv;
    }
}

// ---------------------------------------------------------------------------
// gemm_adj: triangular linear grid. Whole K=128 in smem via cp.async.
// Epilogue: zeros into out, tie bitmasks (upper + transposed), fused rowmax.
// ---------------------------------------------------------------------------
__global__ __launch_bounds__(256, 1) void gemm_adj_kernel(float* __restrict__ out,
                                                          int N, int npad,
                                                          int wpr) {
    // triangular decode: blockIdx.x -> (bx, by) with by <= bx
    int u = blockIdx.x;
    int bx = (int)((sqrtf(8.0f * (float)u + 1.0f) - 1.0f) * 0.5f);
    while ((bx + 1) * (bx + 2) / 2 <= u) bx++;
    while (bx * (bx + 1) / 2 > u) bx--;
    int by = u - bx * (bx + 1) / 2;
    const int bm = by * 128, bn = bx * 128;
    const bool diag = (bx == by);

    extern __shared__ float sm[];
    float* Asf = sm;
    float* Bsf = sm + 16384;

    const int t = threadIdx.x;
    const int tx = t & 15, ty = t >> 4;
    const int lane = t & 31;
    const int warp = t >> 5;

    // ---- load whole K slab via cp.async ----
    {
        const float4* Xv = reinterpret_cast<const float4*>(g_Xt);
        const float4* Yv = reinterpret_cast<const float4*>(g_Yt);
        uint32_t As_s = (uint32_t)__cvta_generic_to_shared(Asf);
        uint32_t Bs_s = (uint32_t)__cvta_generic_to_shared(Bsf);
        const int np4 = npad >> 2;
        const int bm4 = bm >> 2, bn4 = bn >> 2;
#pragma unroll
        for (int e = 0; e < 16; e++) {
            int q = e * 256 + t;
            int k = q >> 5;
            int r4 = q & 31;
            cp_async16(As_s + q * 16, &Xv[(size_t)k * np4 + bm4 + r4]);
            cp_async16(Bs_s + q * 16, &Yv[(size_t)k * np4 + bn4 + r4]);
        }
        asm volatile("cp.async.commit_group;");
        asm volatile("cp.async.wait_group 0;");
    }
    __syncthreads();

    float acc[8][8];
#pragma unroll
    for (int i = 0; i < 8; i++)
#pragma unroll
        for (int j = 0; j < 8; j++) acc[i][j] = 0.0f;

#pragma unroll 4
    for (int k = 0; k < 128; k++) {
        const float* ak = Asf + k * 128;
        const float* bk = Bsf + k * 128;
        float4 a0 = *(const float4*)(ak + ty * 4);
        float4 a1 = *(const float4*)(ak + 64 + ty * 4);
        float4 b0 = *(const float4*)(bk + tx * 4);
        float4 b1 = *(const float4*)(bk + 64 + tx * 4);
        float ra[8] = {a0.x, a0.y, a0.z, a0.w, a1.x, a1.y, a1.z, a1.w};
        float rb[8] = {b0.x, b0.y, b0.z, b0.w, b1.x, b1.y, b1.z, b1.w};
#pragma unroll
        for (int i = 0; i < 8; i++)
#pragma unroll
            for (int j = 0; j < 8; j++)
                acc[i][j] = fmaf(ra[i], rb[j], acc[i][j]);
    }

    // ---- t = tanh_xla(3*acc) in regs ----
#pragma unroll
    for (int i = 0; i < 8; i++)
#pragma unroll
        for (int j = 0; j < 8; j++) acc[i][j] = tanh_xla(3.0f * acc[i][j]);

    __syncthreads();  // As/Bs dead; smem overlays follow

    unsigned* mUw = reinterpret_cast<unsigned*>(sm);         // [128][32]
    unsigned* mLw = reinterpret_cast<unsigned*>(sm) + 4096;  // [128][32]
    float* sMaxI = sm + 8192;                                // [128]
    float* sPartJ = sm + 8320;                               // [8][132]

    int R[8], C[8];
#pragma unroll
    for (int v = 0; v < 4; v++) {
        R[v] = ty * 4 + v;      R[4 + v] = 64 + ty * 4 + v;
        C[v] = tx * 4 + v;      C[4 + v] = 64 + tx * 4 + v;
    }

    const unsigned satb = __float_as_uint(sat_val());
    const unsigned nsatb = satb ^ 0x80000000u;

    // upper-mask nibbles: bits over cols
#pragma unroll
    for (int ii = 0; ii < 8; ii++) {
#pragma unroll
        for (int q = 0; q < 2; q++) {
            unsigned nib = 0;
#pragma unroll
            for (int b = 0; b < 4; b++)
                nib |= (__float_as_uint(acc[ii][q * 4 + b]) == satb) << b;
            mUw[R[ii] * 32 + 16 * q + tx] = nib;
        }
    }
    // lower-mask nibbles: bits over rows (transposed), value == -satval
    if (!diag) {
#pragma unroll
        for (int jj = 0; jj < 8; jj++) {
#pragma unroll
            for (int g = 0; g < 2; g++) {
                unsigned nib = 0;
#pragma unroll
                for (int v = 0; v < 4; v++)
                    nib |= (__float_as_uint(acc[g * 4 + v][jj]) == nsatb) << v;
                mLw[C[jj] * 32 + 16 * g + ty] = nib;
            }
        }
    }

    // I-row maxes of max(t,0)
#pragma unroll
    for (int ii = 0; ii < 8; ii++) {
        float m = acc[ii][0];
#pragma unroll
        for (int jj = 1; jj < 8; jj++) m = fmaxf(m, acc[ii][jj]);
        m = fmaxf(m, 0.0f);
#pragma unroll
        for (int s = 1; s < 16; s <<= 1)
            m = fmaxf(m, __shfl_xor_sync(0xffffffffu, m, s));
        if (tx == 0) sMaxI[R[ii]] = m;
    }
    // J-col maxes of max(-t,0)
    if (!diag) {
        float mj[8];
#pragma unroll
        for (int jj = 0; jj < 8; jj++) {
            float m = -acc[0][jj];
#pragma unroll
            for (int ii = 1; ii < 8; ii++) m = fmaxf(m, -acc[ii][jj]);
            m = fmaxf(m, 0.0f);
            m = fmaxf(m, __shfl_xor_sync(0xffffffffu, m, 16));
            mj[jj] = m;
        }
        if (lane < 16) {
#pragma unroll
            for (int jj = 0; jj < 8; jj++) sPartJ[warp * 132 + C[jj]] = mj[jj];
        }
    }

    // ---- zero-fill d_out for owned tiles (hides under compute of other CTAs)
    {
        const float4 z4 = make_float4(0.0f, 0.0f, 0.0f, 0.0f);
#pragma unroll
        for (int p = 0; p < 16; p++) {
            int e = p * 256 + t;
            int r = e >> 5;
            int c = (e & 31) * 4;
            int gi = bm + r, gj = bn + c;
            if (gi < N) {
                if (gj + 3 < N)
                    *(float4*)&out[(size_t)gi * N + gj] = z4;
                else
                    for (int b = 0; b < 4; b++)
                        if (gj + b < N) out[(size_t)gi * N + gj + b] = 0.0f;
            }
            if (!diag) {
                int gi2 = bn + r, gj2 = bm + c;
                if (gi2 < N) {
                    if (gj2 + 3 < N)
                        *(float4*)&out[(size_t)gi2 * N + gj2] = z4;
                    else
                        for (int b = 0; b < 4; b++)
                            if (gj2 + b < N) out[(size_t)gi2 * N + gj2 + b] = 0.0f;
                }
            }
        }
    }

    __syncthreads();

    // ---- pack + store masks ----
    const int bnw = bn >> 5, bmw = bm >> 5;
#pragma unroll
    for (int s = 0; s < 2; s++) {
        int w = s * 256 + t;     // 0..511
        int r = w >> 2, ww = w & 3;
        unsigned wd = 0;
#pragma unroll
        for (int b = 0; b < 8; b++) wd |= mUw[r * 32 + ww * 8 + b] << (4 * b);
        g_mask[(size_t)(bm + r) * wpr + bnw + ww] = wd;
        if (!diag) {
            unsigned wl = 0;
#pragma unroll
            for (int b = 0; b < 8; b++)
                wl |= mLw[r * 32 + ww * 8 + b] << (4 * b);
            g_mask[(size_t)(bn + r) * wpr + bmw + ww] = wl;
        }
    }

    // ---- rowmax atomics ----
    if (t < 128) {
        int gi = bm + t;
        if (gi < npad) atomicMax(&g_rowmax[gi], sanitize_pos(sMaxI[t]));
        if (!diag) {
            float m = sPartJ[t];
#pragma unroll
            for (int w = 1; w < 8; w++) m = fmaxf(m, sPartJ[w * 132 + t]);
            int gj = bn + t;
            if (gj < npad) atomicMax(&g_rowmax[gj], sanitize_pos(m));
        }
    }
}

// ---------------------------------------------------------------------------
// topk_mask: warp per row. Scan mask, scatter satval at 20 smallest set bits.
// Rows with rowmax != satval OR fewer than 20 ties -> fallback list.
// ---------------------------------------------------------------------------
__global__ __launch_bounds__(256) void topk_mask_kernel(float* __restrict__ out,
                                                        int N, int wpr) {
    const int row = blockIdx.x * 8 + (threadIdx.x >> 5);
    const int lane = threadIdx.x & 31;
    if (row >= N) return;

    const unsigned satb = __float_as_uint(sat_val());
    unsigned rm = g_rowmax[row];
    if (rm != satb) {
        if (lane == 0) {
            int p = atomicAdd(&g_fb_cnt, 1);
            g_fb_list[p] = row;
        }
        return;
    }

    const float sv = sat_val();
    int found = 0;
    const int nchunks = (wpr + 31) >> 5;
    for (int chunk = 0; chunk < nchunks; chunk++) {
        int wi = chunk * 32 + lane;
        unsigned w = (wi < wpr) ? g_mask[(size_t)row * wpr + wi] : 0u;
        int c = __popc(w);
        int incl = c;
#pragma unroll
        for (int s = 1; s < 32; s <<= 1) {
            int o = __shfl_up_sync(0xffffffffu, incl, s);
            if (lane >= s) incl += o;
        }
        int excl = incl - c;
        int total = __shfl_sync(0xffffffffu, incl, 31);
        int base = found + excl;
        while (w && base < 20) {
            int b = __ffs(w) - 1;
            w &= w - 1;
            out[(size_t)row * N + (size_t)wi * 32 + b] = sv;
            base++;
        }
        found += total;
        if (found >= 20) break;
    }
    if (found < 20) {
        if (lane == 0) {
            int p = atomicAdd(&g_fb_cnt, 1);
            g_fb_list[p] = row;
        }
    }
}

// ---------------------------------------------------------------------------
// fallback: exact recompute + general top-20 for flagged rows (expected 0).
// ---------------------------------------------------------------------------
__global__ __launch_bounds__(256) void fallback_kernel(float* __restrict__ out,
                                                       int N, int npad) {
    __shared__ float sX[128];
    __shared__ __align__(16) float srow[10016];
    __shared__ unsigned long long red[256];
    __shared__ int selIdx[20];
    __shared__ float selVal[20];

    const int t = threadIdx.x;
    const int cnt = g_fb_cnt;

    for (int ri = blockIdx.x; ri < cnt; ri += gridDim.x) {
        const int row = g_fb_list[ri];
        if (t < 128) sX[t] = g_Xt[(size_t)t * npad + row];
        __syncthreads();

        for (int j = t; j < N; j += 256) {
            float a = 0.0f;
#pragma unroll 4
            for (int k = 0; k < 128; k++)
                a = fmaf(sX[k], g_Yt[(size_t)k * npad + j], a);
            srow[j] = fmaxf(tanh_xla(3.0f * a), 0.0f);
        }
        __syncthreads();

        unsigned long long cand[20];
#pragma unroll
        for (int c = 0; c < 20; c++) cand[c] = 0ull;
        unsigned long long curMin = 0ull;
        for (int q = t; q < N; q += 256) {
            unsigned vb = __float_as_uint(srow[q]);
            if (vb == 0x80000000u) vb = 0u;
            unsigned long long key =
                ((unsigned long long)vb << 32) |
                (unsigned long long)(0xFFFFFFFFu - (unsigned)q);
            if (key > curMin) {
                bool done = false;
#pragma unroll
                for (int c = 0; c < 20; c++) {
                    if (!done && cand[c] == curMin) {
                        cand[c] = key;
                        done = true;
                    }
                }
                unsigned long long m = cand[0];
#pragma unroll
                for (int c = 1; c < 20; c++) m = (cand[c] < m) ? cand[c] : m;
                curMin = m;
            }
        }
        for (int it = 0; it < 20; it++) {
            unsigned long long m = cand[0];
#pragma unroll
            for (int c = 1; c < 20; c++) m = (cand[c] > m) ? cand[c] : m;
            red[t] = m;
            __syncthreads();
            for (int s = 128; s >= 32; s >>= 1) {
                if (t < s) {
                    unsigned long long o = red[t + s];
                    if (o > red[t]) red[t] = o;
                }
                __syncthreads();
            }
            if (t < 32) {
                unsigned long long g = red[t];
#pragma unroll
                for (int s = 16; s; s >>= 1) {
                    unsigned long long o = __shfl_xor_sync(0xffffffffu, g, s);
                    if (o > g) g = o;
                }
                if (t == 0) red[0] = g;
            }
            __syncthreads();
            unsigned long long g = red[0];
            if (t == 0) {
                if (g != 0ull) {
                    selIdx[it] =
                        (int)(0xFFFFFFFFu - (unsigned)(g & 0xFFFFFFFFull));
                    selVal[it] = __uint_as_float((unsigned)(g >> 32));
                } else {
                    selIdx[it] = 0;
                    selVal[it] = 0.0f;
                }
            }
            if (g != 0ull) {
#pragma unroll
                for (int c = 0; c < 20; c++)
                    if (cand[c] == g) cand[c] = 0ull;
            }
            __syncthreads();
        }
        if (t < 20) out[(size_t)row * N + selIdx[t]] = selVal[t];
        __syncthreads();
    }
}

// ---------------------------------------------------------------------------
extern "C" void kernel_launch(void* const* d_in, const int* in_sizes, int n_in,
                              void* d_out, int out_size) {
    const int* idx = (const int*)d_in[0];
    const float* gEmb = (const float*)d_in[1];
    const float* embW = (const float*)d_in[2];
    const float* fc1w = (const float*)d_in[3];
    const float* fc1b = (const float*)d_in[4];
    float* out = (float*)d_out;

    int N = in_sizes[0];
    int tiles = (N + 127) / 128;
    int npad = tiles * 128;
    int wpr = npad >> 5;
    int tri = tiles * (tiles + 1) / 2;

    static bool attr_set = false;
    if (!attr_set) {
        cudaFuncSetAttribute(gemm_adj_kernel,
                             cudaFuncAttributeMaxDynamicSharedMemorySize,
                             131072);
        attr_set = true;
    }

    prep_kernel<<<npad / 64, 256>>>(idx, gEmb, embW, fc1w, fc1b, N, npad);
    gemm_adj_kernel<<<tri, 256, 131072>>>(out, N, npad, wpr);
    topk_mask_kernel<<<(N + 7) / 8, 256>>>(out, N, wpr);
    fallback_kernel<<<64, 256>>>(out, N, npad);
}

// round 4
// speedup vs baseline: 11.7311x; 3.2474x over previous
#include <cuda_runtime.h>
#include <cstdint>

// ---------------------------------------------------------------------------
// local_graph_creator: adj = relu(tanh(3*(vec1@gEmb.T - gEmb@vec1.T))),
// per-row top-20 (value desc, index asc) binary mask applied.
//
// Output rows are (empirically, rel_err==0.0 across rounds 1-3): zeros plus
// satval at the 20 smallest column indices whose tanh saturates to satval
// bits. Those 20 indices live in the first ~60 columns; so only an exact
// N x 256 STRIP of the score matrix is needed. Rows that don't have >=20
// saturated entries in the strip go to an exact full-row fallback.
//
//   prep:       vec1 = tanh_xla(3*fc1(emb)); pack transposed Xt/Yt.
//   strip:      exact fp32 a for cols [0,256) with the identical k-ascending
//               FMA chain + tanh_xla as all prior (bit-exact) rounds; emits
//               saturation bitmask (8 words/row).
//   topk_strip: warp/row: zero the row (the only O(N^2) traffic), scatter
//               satval at the 20 smallest set bits; <20 -> fallback list.
//   fallback:   exact full-row recompute + general top-20 (expected 0 rows).
// ---------------------------------------------------------------------------

#define MAX_NPAD 10112

__device__ float g_Xt[128 * MAX_NPAD];    // [k][i]  X = [vec1 | -gEmb]
__device__ float g_Yt[128 * MAX_NPAD];    // [k][i]  Y = [gEmb  |  vec1]
__device__ unsigned g_maskS[MAX_NPAD * 8];// strip tie bitmask (256 cols/row)
__device__ int g_fb_cnt;
__device__ int g_fb_list[MAX_NPAD];

__device__ __forceinline__ float tanh_xla(float x) {
    const float kClamp = 7.99881172180175781f;
    float ax = fabsf(x);
    float xc = fminf(fmaxf(x, -kClamp), kClamp);
    float x2 = xc * xc;
    float p = -2.76076847742355e-16f;
    p = fmaf(x2, p, 2.00018790482477e-13f);
    p = fmaf(x2, p, -8.60467152213735e-11f);
    p = fmaf(x2, p, 5.12229709037114e-08f);
    p = fmaf(x2, p, 1.48572235717979e-05f);
    p = fmaf(x2, p, 6.37261928875436e-04f);
    p = fmaf(x2, p, 4.89352455891786e-03f);
    p = xc * p;
    float q = fmaf(x2, 1.19825839466702e-06f, 1.18534705686654e-04f);
    q = fmaf(x2, q, 2.26843463243900e-03f);
    q = fmaf(x2, q, 4.89352518554385e-03f);
    float r = p / q;
    return (ax < 0.0004f) ? x : r;
}

__device__ __forceinline__ float sat_val() { return tanh_xla(8.0f); }

__device__ __forceinline__ void cp_async16(uint32_t saddr, const void* gaddr) {
    asm volatile("cp.async.cg.shared.global [%0], [%1], 16;" ::
                 "r"(saddr), "l"(gaddr));
}

// ---------------------------------------------------------------------------
// prep: 64 rows per block; vec1 via smem-resident fc1_w^T; coalesced
// transposed packing of Xt/Yt through smem. Zeroes fallback counter.
// ---------------------------------------------------------------------------
__global__ __launch_bounds__(256) void prep_kernel(
    const int* __restrict__ idx, const float* __restrict__ gEmb,
    const float* __restrict__ embW, const float* __restrict__ fc1w,
    const float* __restrict__ fc1b, int N, int npad) {
    __shared__ float ws[64 * 65];   // phase A: fc1w^T; phase B/C: gEmb
    __shared__ float sv[64 * 65];   // vec1 transposed [d][i_local]
    __shared__ float bs[64];
    const int t = threadIdx.x;
    const int bi0 = blockIdx.x * 64;

    if (blockIdx.x == 0 && t == 0) g_fb_cnt = 0;

    for (int e = t; e < 64 * 64; e += 256) {
        int d = e >> 6, k = e & 63;
        ws[k * 65 + d] = fc1w[e];
    }
    if (t < 64) bs[t] = fc1b[t];
    __syncthreads();

    const int d = t & 63;
    const int rq = t >> 6;
#pragma unroll
    for (int rr = 0; rr < 16; rr++) {
        int il = rr * 4 + rq;
        int i = bi0 + il;
        float v = 0.0f;
        if (i < N) {
            int src = idx[i];
            const float* er = embW + (size_t)src * 64;
            float acc = 0.0f;
#pragma unroll
            for (int k = 0; k < 64; k++) acc = fmaf(er[k], ws[k * 65 + d], acc);
            acc += bs[d];
            v = tanh_xla(3.0f * acc);
        }
        sv[d * 65 + il] = v;
    }
    __syncthreads();

#pragma unroll
    for (int rr = 0; rr < 16; rr++) {
        int il = rr * 4 + rq;
        int i = bi0 + il;
        float g = (i < N) ? gEmb[(size_t)i * 64 + d] : 0.0f;
        ws[d * 65 + il] = g;
    }
    __syncthreads();

#pragma unroll
    for (int p = 0; p < 8; p++) {
        int e = p * 256 + t;
        int dd = e >> 4;
        int i4 = (e & 15) * 4;
        float4 xv, yv;
        if (dd < 64) {
            xv.x = sv[dd * 65 + i4 + 0]; xv.y = sv[dd * 65 + i4 + 1];
            xv.z = sv[dd * 65 + i4 + 2]; xv.w = sv[dd * 65 + i4 + 3];
            yv.x = ws[dd * 65 + i4 + 0]; yv.y = ws[dd * 65 + i4 + 1];
            yv.z = ws[dd * 65 + i4 + 2]; yv.w = ws[dd * 65 + i4 + 3];
        } else {
            int dl = dd - 64;
            xv.x = -ws[dl * 65 + i4 + 0]; xv.y = -ws[dl * 65 + i4 + 1];
            xv.z = -ws[dl * 65 + i4 + 2]; xv.w = -ws[dl * 65 + i4 + 3];
            yv.x = sv[dl * 65 + i4 + 0];  yv.y = sv[dl * 65 + i4 + 1];
            yv.z = sv[dl * 65 + i4 + 2];  yv.w = sv[dl * 65 + i4 + 3];
        }
        *(float4*)&g_Xt[(size_t)dd * npad + bi0 + i4] = xv;
        *(float4*)&g_Yt[(size_t)dd * npad + bi0 + i4] = yv;
    }
}

// ---------------------------------------------------------------------------
// strip: 64 rows x 128 cols per CTA, grid (2, npad/64). Whole K=128 in smem.
// Per-element k-ascending fp32 fmaf chain, bit-identical to prior rounds.
// Emits saturation bitmask words (cols bn..bn+127 -> words (bn>>5)..+3).
// ---------------------------------------------------------------------------
__global__ __launch_bounds__(256, 2) void strip_kernel(int npad) {
    const int bm = blockIdx.y * 64;
    const int bn = blockIdx.x * 128;

    extern __shared__ float sm[];
    float* Asf = sm;           // [k][r] 128 x 64
    float* Bsf = sm + 8192;    // [k][r] 128 x 128

    const int t = threadIdx.x;
    const int tx = t & 15, ty = t >> 4;

    {
        const float4* Xv = reinterpret_cast<const float4*>(g_Xt);
        const float4* Yv = reinterpret_cast<const float4*>(g_Yt);
        uint32_t As_s = (uint32_t)__cvta_generic_to_shared(Asf);
        uint32_t Bs_s = (uint32_t)__cvta_generic_to_shared(Bsf);
        const int np4 = npad >> 2;
        const int bm4 = bm >> 2, bn4 = bn >> 2;
#pragma unroll
        for (int e = 0; e < 8; e++) {
            int q = e * 256 + t;      // 0..2047
            int k = q >> 4;           // 0..127
            int r4 = q & 15;
            cp_async16(As_s + q * 16, &Xv[(size_t)k * np4 + bm4 + r4]);
        }
#pragma unroll
        for (int e = 0; e < 16; e++) {
            int q = e * 256 + t;      // 0..4095
            int k = q >> 5;
            int r4 = q & 31;
            cp_async16(Bs_s + q * 16, &Yv[(size_t)k * np4 + bn4 + r4]);
        }
        asm volatile("cp.async.commit_group;");
        asm volatile("cp.async.wait_group 0;");
    }
    __syncthreads();

    float acc[4][8];
#pragma unroll
    for (int i = 0; i < 4; i++)
#pragma unroll
        for (int j = 0; j < 8; j++) acc[i][j] = 0.0f;

#pragma unroll 4
    for (int k = 0; k < 128; k++) {
        const float* ak = Asf + k * 64;
        const float* bk = Bsf + k * 128;
        float4 a0 = *(const float4*)(ak + ty * 4);
        float4 b0 = *(const float4*)(bk + tx * 4);
        float4 b1 = *(const float4*)(bk + 64 + tx * 4);
        float ra[4] = {a0.x, a0.y, a0.z, a0.w};
        float rb[8] = {b0.x, b0.y, b0.z, b0.w, b1.x, b1.y, b1.z, b1.w};
#pragma unroll
        for (int i = 0; i < 4; i++)
#pragma unroll
            for (int j = 0; j < 8; j++)
                acc[i][j] = fmaf(ra[i], rb[j], acc[i][j]);
    }

#pragma unroll
    for (int i = 0; i < 4; i++)
#pragma unroll
        for (int j = 0; j < 8; j++) acc[i][j] = tanh_xla(3.0f * acc[i][j]);

    __syncthreads();  // As/Bs dead

    unsigned* mUw = reinterpret_cast<unsigned*>(sm);  // [64][32] nibbles
    const unsigned satb = __float_as_uint(sat_val());

#pragma unroll
    for (int ii = 0; ii < 4; ii++) {
        int r = ty * 4 + ii;
#pragma unroll
        for (int q = 0; q < 2; q++) {
            unsigned nib = 0;
#pragma unroll
            for (int b = 0; b < 4; b++)
                nib |= (__float_as_uint(acc[ii][q * 4 + b]) == satb) << b;
            mUw[r * 32 + 16 * q + tx] = nib;
        }
    }
    __syncthreads();

    // pack: 64 rows x 4 words = 256 words, one per thread
    {
        int r = t >> 2, ww = t & 3;
        unsigned wd = 0;
#pragma unroll
        for (int b = 0; b < 8; b++) wd |= mUw[r * 32 + ww * 8 + b] << (4 * b);
        g_maskS[(size_t)(bm + r) * 8 + (bn >> 5) + ww] = wd;
    }
}

// ---------------------------------------------------------------------------
// topk_strip: warp per row. Zero the row (float4), then scatter satval at the
// 20 smallest set bits of the 256-col strip mask. <20 bits -> fallback list.
// ---------------------------------------------------------------------------
__global__ __launch_bounds__(256) void topk_strip_kernel(float* __restrict__ out,
                                                         int N) {
    const int row = blockIdx.x * 8 + (threadIdx.x >> 5);
    const int lane = threadIdx.x & 31;
    if (row >= N) return;

    float* rowp = out + (size_t)row * N;
    const int nv = N >> 2;
    const float4 z = make_float4(0.0f, 0.0f, 0.0f, 0.0f);
    for (int q = lane; q < nv; q += 32) reinterpret_cast<float4*>(rowp)[q] = z;
    for (int q = nv * 4 + lane; q < N; q += 32) rowp[q] = 0.0f;
    __syncwarp();

    unsigned w = (lane < 8) ? g_maskS[(size_t)row * 8 + lane] : 0u;
    int c = __popc(w);
    int incl = c;
#pragma unroll
    for (int s = 1; s < 32; s <<= 1) {
        int o = __shfl_up_sync(0xffffffffu, incl, s);
        if (lane >= s) incl += o;
    }
    int excl = incl - c;
    int total = __shfl_sync(0xffffffffu, incl, 31);

    if (total >= 20) {
        const float sv = sat_val();
        int base = excl;
        unsigned ww = w;
        while (ww && base < 20) {
            int b = __ffs(ww) - 1;
            ww &= ww - 1;
            rowp[lane * 32 + b] = sv;
            base++;
        }
    } else if (lane == 0) {
        int p = atomicAdd(&g_fb_cnt, 1);
        g_fb_list[p] = row;
    }
}

// ---------------------------------------------------------------------------
// fallback: exact full-row recompute + general top-20 (expected 0 rows).
// ---------------------------------------------------------------------------
__global__ __launch_bounds__(256) void fallback_kernel(float* __restrict__ out,
                                                       int N, int npad) {
    __shared__ float sX[128];
    __shared__ __align__(16) float srow[10016];
    __shared__ unsigned long long red[256];
    __shared__ int selIdx[20];
    __shared__ float selVal[20];

    const int t = threadIdx.x;
    const int cnt = g_fb_cnt;

    for (int ri = blockIdx.x; ri < cnt; ri += gridDim.x) {
        const int row = g_fb_list[ri];
        if (t < 128) sX[t] = g_Xt[(size_t)t * npad + row];
        __syncthreads();

        for (int j = t; j < N; j += 256) {
            float a = 0.0f;
#pragma unroll 4
            for (int k = 0; k < 128; k++)
                a = fmaf(sX[k], g_Yt[(size_t)k * npad + j], a);
            srow[j] = fmaxf(tanh_xla(3.0f * a), 0.0f);
        }
        __syncthreads();

        unsigned long long cand[20];
#pragma unroll
        for (int c = 0; c < 20; c++) cand[c] = 0ull;
        unsigned long long curMin = 0ull;
        for (int q = t; q < N; q += 256) {
            unsigned vb = __float_as_uint(srow[q]);
            if (vb == 0x80000000u) vb = 0u;
            unsigned long long key =
                ((unsigned long long)vb << 32) |
                (unsigned long long)(0xFFFFFFFFu - (unsigned)q);
            if (key > curMin) {
                bool done = false;
#pragma unroll
                for (int c = 0; c < 20; c++) {
                    if (!done && cand[c] == curMin) {
                        cand[c] = key;
                        done = true;
                    }
                }
                unsigned long long m = cand[0];
#pragma unroll
                for (int c = 1; c < 20; c++) m = (cand[c] < m) ? cand[c] : m;
                curMin = m;
            }
        }
        for (int it = 0; it < 20; it++) {
            unsigned long long m = cand[0];
#pragma unroll
            for (int c = 1; c < 20; c++) m = (cand[c] > m) ? cand[c] : m;
            red[t] = m;
            __syncthreads();
            for (int s = 128; s >= 32; s >>= 1) {
                if (t < s) {
                    unsigned long long o = red[t + s];
                    if (o > red[t]) red[t] = o;
                }
                __syncthreads();
            }
            if (t < 32) {
                unsigned long long g = red[t];
#pragma unroll
                for (int s = 16; s; s >>= 1) {
                    unsigned long long o = __shfl_xor_sync(0xffffffffu, g, s);
                    if (o > g) g = o;
                }
                if (t == 0) red[0] = g;
            }
            __syncthreads();
            unsigned long long g = red[0];
            if (t == 0) {
                if (g != 0ull) {
                    selIdx[it] =
                        (int)(0xFFFFFFFFu - (unsigned)(g & 0xFFFFFFFFull));
                    selVal[it] = __uint_as_float((unsigned)(g >> 32));
                } else {
                    selIdx[it] = 0;
                    selVal[it] = 0.0f;
                }
            }
            if (g != 0ull) {
#pragma unroll
                for (int c = 0; c < 20; c++)
                    if (cand[c] == g) cand[c] = 0ull;
            }
            __syncthreads();
        }
        if (t < 20) out[(size_t)row * N + selIdx[t]] = selVal[t];
        __syncthreads();
    }
}

// ---------------------------------------------------------------------------
extern "C" void kernel_launch(void* const* d_in, const int* in_sizes, int n_in,
                              void* d_out, int out_size) {
    const int* idx = (const int*)d_in[0];
    const float* gEmb = (const float*)d_in[1];
    const float* embW = (const float*)d_in[2];
    const float* fc1w = (const float*)d_in[3];
    const float* fc1b = (const float*)d_in[4];
    float* out = (float*)d_out;

    int N = in_sizes[0];
    int tiles64 = (N + 63) / 64;
    int npad = ((N + 127) / 128) * 128;
    tiles64 = npad / 64;

    static bool attr_set = false;
    if (!attr_set) {
        cudaFuncSetAttribute(strip_kernel,
                             cudaFuncAttributeMaxDynamicSharedMemorySize,
                             98304);
        attr_set = true;
    }

    prep_kernel<<<npad / 64, 256>>>(idx, gEmb, embW, fc1w, fc1b, N, npad);
    strip_kernel<<<dim3(2, tiles64), 256, 98304>>>(npad);
    topk_strip_kernel<<<(N + 7) / 8, 256>>>(out, N);
    fallback_kernel<<<64, 256>>>(out, N, npad);
}